// round 5
// baseline (speedup 1.0000x reference)
#include <cuda_runtime.h>
#include <cuda_bf16.h>
#include <cstdint>

// Shapes (fixed per problem)
#define BB 8
#define TT 2048
#define CC 768
#define WDIM 512
#define TD 384
#define CD 3072
#define ROWS (BB * TT)          // 16384

// weight pack offsets (elements)
#define OFF_G1 0
#define OFF_G2 589824
#define OFF_M1 1179648
#define OFF_M2 1327104
#define OFF_GS 1474560
#define OFF_MS 3833856
#define OFF_R1 5013504
#define OFF_R2 5603328
#define WTOT   5898240

// ---------------- scratch (device globals; no allocation allowed) ----------
__device__ float BUF_HF [ROWS * CD];       // fp32 GLU inputs (largest GEMM out)
__device__ float BUF_XLN[ROWS * CC];       // fp32 ln1 out (residual for step6)
__device__ float BUF_X2 [ROWS * CC];       // fp32 (residual for step8 + ln2 in)
__device__ float BUF_S1 [BB * TD];
__device__ float BUF_S2 [BB * TD];
__device__ float BUF_SS [BB * (CD/2)];

__device__ __nv_bfloat16 S_XLNh[ROWS * CC],      S_XLNl[ROWS * CC];
__device__ __nv_bfloat16 S_ACTh[ROWS * (CD/2)],  S_ACTl[ROWS * (CD/2)];
__device__ __nv_bfloat16 S_H1h [BB * TD * TT],   S_H1l [BB * TD * TT];   // (b,d,t)
__device__ __nv_bfloat16 S_H2h [ROWS * TD],      S_H2l [ROWS * TD];
__device__ __nv_bfloat16 S_MIXh[BB * TD * CC],   S_MIXl[BB * TD * CC];
__device__ __nv_bfloat16 S_X3h [ROWS * CC],      S_X3l [ROWS * CC];
__device__ __nv_bfloat16 S_Wh  [WTOT],           S_Wl  [WTOT];

// ---------------- helpers ---------------------------------------------------
__device__ __forceinline__ float gelu_f(float v) {
    return 0.5f * v * (1.0f + erff(v * 0.70710678118654752f));
}
__device__ __forceinline__ void split_bf16(float v, __nv_bfloat16& h, __nv_bfloat16& l) {
    h = __float2bfloat16_rn(v);
    l = __float2bfloat16_rn(v - __bfloat162float(h));
}
__device__ __forceinline__ void cp16(void* smem, const void* gmem) {
    uint32_t s = (uint32_t)__cvta_generic_to_shared(smem);
    asm volatile("cp.async.cg.shared.global [%0], [%1], 16;" :: "r"(s), "l"(gmem));
}
__device__ __forceinline__ void cp_commit() { asm volatile("cp.async.commit_group;"); }
__device__ __forceinline__ void cp_wait0()  { asm volatile("cp.async.wait_group 0;"); }

__device__ __forceinline__ void ldsm4(uint32_t* r, const void* p) {
    uint32_t a = (uint32_t)__cvta_generic_to_shared(p);
    asm volatile("ldmatrix.sync.aligned.m8n8.x4.shared.b16 {%0,%1,%2,%3}, [%4];"
                 : "=r"(r[0]), "=r"(r[1]), "=r"(r[2]), "=r"(r[3]) : "r"(a));
}
__device__ __forceinline__ void ldsm4t(uint32_t* r, const void* p) {
    uint32_t a = (uint32_t)__cvta_generic_to_shared(p);
    asm volatile("ldmatrix.sync.aligned.m8n8.x4.trans.shared.b16 {%0,%1,%2,%3}, [%4];"
                 : "=r"(r[0]), "=r"(r[1]), "=r"(r[2]), "=r"(r[3]) : "r"(a));
}
__device__ __forceinline__ void mma_bf16(float* d, const uint32_t* a, const uint32_t* b) {
    asm volatile(
        "mma.sync.aligned.m16n8k16.row.col.f32.bf16.bf16.f32 "
        "{%0,%1,%2,%3}, {%4,%5,%6,%7}, {%8,%9}, {%0,%1,%2,%3};"
        : "+f"(d[0]), "+f"(d[1]), "+f"(d[2]), "+f"(d[3])
        : "r"(a[0]), "r"(a[1]), "r"(a[2]), "r"(a[3]), "r"(b[0]), "r"(b[1]));
}

// ---------------- LayerNorm (+ bf16 split output) ----------------------------
__global__ void ln_split_kernel(const float* __restrict__ x,
                                const float* __restrict__ g,
                                const float* __restrict__ b,
                                float* __restrict__ yf,          // optional fp32 out
                                __nv_bfloat16* __restrict__ yh,
                                __nv_bfloat16* __restrict__ yl, int C) {
    __shared__ float red[2][8];
    long row = blockIdx.x;
    const float* xr = x + row * C;
    float s = 0.f, s2 = 0.f;
    for (int c = threadIdx.x; c < C; c += blockDim.x) {
        float v = xr[c];
        s += v; s2 += v * v;
    }
    #pragma unroll
    for (int o = 16; o; o >>= 1) {
        s  += __shfl_xor_sync(0xFFFFFFFFu, s,  o);
        s2 += __shfl_xor_sync(0xFFFFFFFFu, s2, o);
    }
    int w = threadIdx.x >> 5, l = threadIdx.x & 31;
    if (l == 0) { red[0][w] = s; red[1][w] = s2; }
    __syncthreads();
    if (threadIdx.x < 32) {
        s  = (l < 8) ? red[0][l] : 0.f;
        s2 = (l < 8) ? red[1][l] : 0.f;
        #pragma unroll
        for (int o = 4; o; o >>= 1) {
            s  += __shfl_xor_sync(0xFFFFFFFFu, s,  o);
            s2 += __shfl_xor_sync(0xFFFFFFFFu, s2, o);
        }
        if (l == 0) { red[0][0] = s; red[1][0] = s2; }
    }
    __syncthreads();
    float mu  = red[0][0] / C;
    float var = red[1][0] / C - mu * mu;
    float inv = rsqrtf(var + 1e-6f);
    for (int c = threadIdx.x; c < C; c += blockDim.x) {
        float v = (xr[c] - mu) * inv * g[c] + b[c];
        if (yf) yf[row * C + c] = v;
        __nv_bfloat16 h, lo;
        split_bf16(v, h, lo);
        yh[row * C + c] = h;
        yl[row * C + c] = lo;
    }
}

// ---------------- weight -> hi/lo bf16 split --------------------------------
__global__ void cvt_split_kernel(const float4* __restrict__ in,
                                 __nv_bfloat16* __restrict__ oh,
                                 __nv_bfloat16* __restrict__ ol, int n4) {
    int idx = blockIdx.x * blockDim.x + threadIdx.x;
    if (idx >= n4) return;
    float4 v = in[idx];
    __nv_bfloat16 h[4], l[4];
    split_bf16(v.x, h[0], l[0]); split_bf16(v.y, h[1], l[1]);
    split_bf16(v.z, h[2], l[2]); split_bf16(v.w, h[3], l[3]);
    *(__nv_bfloat162*)(oh + 4L*idx    ) = __nv_bfloat162(h[0], h[1]);
    *(__nv_bfloat162*)(oh + 4L*idx + 2) = __nv_bfloat162(h[2], h[3]);
    *(__nv_bfloat162*)(ol + 4L*idx    ) = __nv_bfloat162(l[0], l[1]);
    *(__nv_bfloat162*)(ol + 4L*idx + 2) = __nv_bfloat162(l[2], l[3]);
}

// ---------------- tiny style-projection -------------------------------------
__global__ void style_s_kernel(const float* __restrict__ w,
                               const float* __restrict__ sW,
                               const float* __restrict__ sb,
                               float* __restrict__ out, int sel, int N) {
    int idx = blockIdx.x * blockDim.x + threadIdx.x;
    if (idx >= BB * N) return;
    int bi = idx / N, n = idx - bi * N;
    const float* wr = w + bi * (2 * WDIM) + sel * WDIM;
    float acc = sb[n];
    for (int k = 0; k < WDIM; k++) acc += wr[k] * sW[(long)k * N + n];
    out[idx] = acc;
}

// ---------------- GLU (+style scale) -> split bf16 --------------------------
__global__ void glu_split_kernel(const float4* __restrict__ hbuf,
                                 const float4* __restrict__ s,
                                 __nv_bfloat16* __restrict__ oh,
                                 __nv_bfloat16* __restrict__ ol,
                                 int halfN4, long totalRows) {
    long total = totalRows * (long)halfN4;
    long idx = (long)blockIdx.x * blockDim.x + threadIdx.x;
    if (idx >= total) return;
    long row = idx / halfN4;
    int  j   = (int)(idx - row * halfN4);
    const float4* hr = hbuf + row * (2L * halfN4);
    float4 a  = hr[j];
    float4 gt = hr[j + halfN4];
    float4 v;
    v.x = a.x / (1.f + __expf(-gt.x));
    v.y = a.y / (1.f + __expf(-gt.y));
    v.z = a.z / (1.f + __expf(-gt.z));
    v.w = a.w / (1.f + __expf(-gt.w));
    if (s) {
        float4 sv = s[(row >> 11) * (long)halfN4 + j];
        v.x *= sv.x; v.y *= sv.y; v.z *= sv.z; v.w *= sv.w;
    }
    __nv_bfloat16 h[4], l[4];
    split_bf16(v.x, h[0], l[0]); split_bf16(v.y, h[1], l[1]);
    split_bf16(v.z, h[2], l[2]); split_bf16(v.w, h[3], l[3]);
    long o = row * (long)halfN4 * 4 + 4L * j;
    *(__nv_bfloat162*)(oh + o    ) = __nv_bfloat162(h[0], h[1]);
    *(__nv_bfloat162*)(oh + o + 2) = __nv_bfloat162(h[2], h[3]);
    *(__nv_bfloat162*)(ol + o    ) = __nv_bfloat162(l[0], l[1]);
    *(__nv_bfloat162*)(ol + o + 2) = __nv_bfloat162(l[2], l[3]);
}

// ---------------- bf16x3 tensor-core GEMM -----------------------------------
// C(M,N) = (Ah+Al) @ (Bh+Bl), dropping lo*lo. All NN:
//   A (M,K) k-contiguous (lda), B (K,N) n-contiguous (ldb).
// Tiles 128x128x16, 256 threads (8 warps 2x4), warp tile 64x32.
// As smem: [m][k] stride 24 bf16 (48B) — ldmatrix.x4, conflict-free.
// Bs smem: [k][n] stride 136 bf16 (272B) — ldmatrix.x4.trans, conflict-free.
#define ASTR 24
#define BSTR 136

template <bool GELU, bool SPLIT, bool TRANSO, bool FP32O>
__global__ __launch_bounds__(256) void gemm_bf3(
    const __nv_bfloat16* __restrict__ Ah, const __nv_bfloat16* __restrict__ Al,
    const __nv_bfloat16* __restrict__ Bh, const __nv_bfloat16* __restrict__ Bl,
    const float* __restrict__ bias, const float* __restrict__ res,
    float* __restrict__ Cf, __nv_bfloat16* __restrict__ Ch, __nv_bfloat16* __restrict__ Cl,
    int N, int K, int lda, int ldb,
    long sA, long sB, long sC, long sRes)
{
    __shared__ __nv_bfloat16 sAh[2][128 * ASTR];
    __shared__ __nv_bfloat16 sAl[2][128 * ASTR];
    __shared__ __nv_bfloat16 sBh[2][16 * BSTR];
    __shared__ __nv_bfloat16 sBl[2][16 * BSTR];

    const int z = blockIdx.z;
    Ah += (long)z * sA;  Al += (long)z * sA;
    Bh += (long)z * sB;  Bl += (long)z * sB;
    const float* resp = res ? res + (long)z * sRes : nullptr;

    const int m0 = blockIdx.y * 128, n0 = blockIdx.x * 128;
    const int tid = threadIdx.x;
    const int lane = tid & 31, wid = tid >> 5;
    const int wm = wid >> 2, wn = wid & 3;
    const int lr = lane >> 2, lc = lane & 3;

    // loader decomposition
    const int aRow = tid >> 1,  aCh = (tid & 1) << 3;    // 128 rows x 2 chunks
    const int bRow = tid >> 4,  bCh = (tid & 15) << 3;   // 16 rows x 16 chunks

    // fragment smem lane offsets
    const int aoff = (lane & 15) * ASTR + ((lane >> 4) << 3);
    const int boff = (lane & 15) * BSTR + ((lane >> 4) << 3);

    float acc[4][4][4];
    #pragma unroll
    for (int i = 0; i < 4; i++)
        #pragma unroll
        for (int j = 0; j < 4; j++) {
            acc[i][j][0] = 0.f; acc[i][j][1] = 0.f;
            acc[i][j][2] = 0.f; acc[i][j][3] = 0.f;
        }

    const int ntiles = K >> 4;

    auto loadTiles = [&](int buf, int k0) {
        const long ao = (long)(m0 + aRow) * lda + k0 + aCh;
        cp16(&sAh[buf][aRow * ASTR + aCh], Ah + ao);
        cp16(&sAl[buf][aRow * ASTR + aCh], Al + ao);
        const long bo = (long)(k0 + bRow) * ldb + n0 + bCh;
        cp16(&sBh[buf][bRow * BSTR + bCh], Bh + bo);
        cp16(&sBl[buf][bRow * BSTR + bCh], Bl + bo);
        cp_commit();
    };

    loadTiles(0, 0);
    cp_wait0();
    __syncthreads();

    for (int it = 0; it < ntiles; it++) {
        const int cur = it & 1;
        const bool more = (it + 1) < ntiles;
        if (more) loadTiles(cur ^ 1, (it + 1) << 4);

        uint32_t fAh[4][4], fAl[4][4], fBh[4][2], fBl[4][2];
        #pragma unroll
        for (int mt = 0; mt < 4; mt++) {
            const int mb = (wm * 64 + mt * 16) * ASTR + aoff;
            ldsm4(fAh[mt], &sAh[cur][mb]);
            ldsm4(fAl[mt], &sAl[cur][mb]);
        }
        #pragma unroll
        for (int p = 0; p < 2; p++) {
            const int nb = wn * 32 + p * 16 + boff;
            uint32_t r[4];
            ldsm4t(r, &sBh[cur][nb]);
            fBh[2*p][0] = r[0]; fBh[2*p][1] = r[1];
            fBh[2*p+1][0] = r[2]; fBh[2*p+1][1] = r[3];
            ldsm4t(r, &sBl[cur][nb]);
            fBl[2*p][0] = r[0]; fBl[2*p][1] = r[1];
            fBl[2*p+1][0] = r[2]; fBl[2*p+1][1] = r[3];
        }

        #pragma unroll
        for (int mt = 0; mt < 4; mt++)
            #pragma unroll
            for (int nt = 0; nt < 4; nt++) {
                mma_bf16(acc[mt][nt], fAh[mt], fBh[nt]);
                mma_bf16(acc[mt][nt], fAh[mt], fBl[nt]);
                mma_bf16(acc[mt][nt], fAl[mt], fBh[nt]);
            }

        if (more) cp_wait0();
        __syncthreads();
    }

    // --- epilogue ---
    #pragma unroll
    for (int mt = 0; mt < 4; mt++) {
        #pragma unroll
        for (int half = 0; half < 2; half++) {
            const int row = m0 + wm * 64 + mt * 16 + lr + half * 8;
            #pragma unroll
            for (int nt = 0; nt < 4; nt++) {
                const int col = n0 + wn * 32 + nt * 8 + 2 * lc;
                float v0 = acc[mt][nt][2 * half + 0];
                float v1 = acc[mt][nt][2 * half + 1];
                if (bias) { v0 += bias[col]; v1 += bias[col + 1]; }
                const long off = (long)row * N + col;
                if (resp) {
                    float2 rv = *(const float2*)&resp[off];
                    v0 += rv.x; v1 += rv.y;
                }
                if (GELU) { v0 = gelu_f(v0); v1 = gelu_f(v1); }
                if (FP32O) {
                    Cf[(long)z * sC + off] = v0;
                    Cf[(long)z * sC + off + 1] = v1;
                }
                if (SPLIT) {
                    __nv_bfloat16 h0, l0, h1, l1;
                    split_bf16(v0, h0, l0);
                    split_bf16(v1, h1, l1);
                    if (TRANSO) {
                        // H1: (b, d, t)  b = row>>11, t = row&2047
                        const long o0 = ((long)(row >> 11) * TD + col) * TT + (row & 2047);
                        const long o1 = o0 + TT;
                        Ch[o0] = h0; Ch[o1] = h1;
                        Cl[o0] = l0; Cl[o1] = l1;
                    } else {
                        const long o = (long)z * sC + off;
                        *(__nv_bfloat162*)(Ch + o) = __nv_bfloat162(h0, h1);
                        *(__nv_bfloat162*)(Cl + o) = __nv_bfloat162(l0, l1);
                    }
                }
            }
        }
    }
}

// ---------------- host-side helpers -----------------------------------------
static void* symp(const void* s) {
    void* p = nullptr;
    cudaGetSymbolAddress(&p, s);
    return p;
}

extern "C" void kernel_launch(void* const* d_in, const int* in_sizes, int n_in,
                              void* d_out, int out_size) {
    const float* x     = (const float*)d_in[0];
    const float* w     = (const float*)d_in[1];
    const float* ln1_g = (const float*)d_in[2];
    const float* ln1_b = (const float*)d_in[3];
    const float* ln2_g = (const float*)d_in[4];
    const float* ln2_b = (const float*)d_in[5];
    const float* g1_W  = (const float*)d_in[6];
    const float* g1_b  = (const float*)d_in[7];
    const float* s1_W  = (const float*)d_in[8];
    const float* s1_b  = (const float*)d_in[9];
    const float* m1_W  = (const float*)d_in[10];
    const float* m1_b  = (const float*)d_in[11];
    const float* g2_W  = (const float*)d_in[12];
    const float* g2_b  = (const float*)d_in[13];
    const float* s2_W  = (const float*)d_in[14];
    const float* s2_b  = (const float*)d_in[15];
    const float* m2_W  = (const float*)d_in[16];
    const float* m2_b  = (const float*)d_in[17];
    const float* gs_W  = (const float*)d_in[18];
    const float* gs_b  = (const float*)d_in[19];
    const float* ss_W  = (const float*)d_in[20];
    const float* ss_b  = (const float*)d_in[21];
    const float* ms_W  = (const float*)d_in[22];
    const float* ms_b  = (const float*)d_in[23];
    const float* r1_W  = (const float*)d_in[24];
    const float* r1_b  = (const float*)d_in[25];
    const float* r2_W  = (const float*)d_in[26];
    const float* r2_b  = (const float*)d_in[27];

    float* HF  = (float*)symp(BUF_HF);
    float* XLN = (float*)symp(BUF_XLN);
    float* X2  = (float*)symp(BUF_X2);
    float* S1  = (float*)symp(BUF_S1);
    float* S2  = (float*)symp(BUF_S2);
    float* SS  = (float*)symp(BUF_SS);
    __nv_bfloat16* XLNh = (__nv_bfloat16*)symp(S_XLNh);
    __nv_bfloat16* XLNl = (__nv_bfloat16*)symp(S_XLNl);
    __nv_bfloat16* ACTh = (__nv_bfloat16*)symp(S_ACTh);
    __nv_bfloat16* ACTl = (__nv_bfloat16*)symp(S_ACTl);
    __nv_bfloat16* H1h  = (__nv_bfloat16*)symp(S_H1h);
    __nv_bfloat16* H1l  = (__nv_bfloat16*)symp(S_H1l);
    __nv_bfloat16* H2h  = (__nv_bfloat16*)symp(S_H2h);
    __nv_bfloat16* H2l  = (__nv_bfloat16*)symp(S_H2l);
    __nv_bfloat16* MIXh = (__nv_bfloat16*)symp(S_MIXh);
    __nv_bfloat16* MIXl = (__nv_bfloat16*)symp(S_MIXl);
    __nv_bfloat16* X3h  = (__nv_bfloat16*)symp(S_X3h);
    __nv_bfloat16* X3l  = (__nv_bfloat16*)symp(S_X3l);
    __nv_bfloat16* Wh   = (__nv_bfloat16*)symp(S_Wh);
    __nv_bfloat16* Wl   = (__nv_bfloat16*)symp(S_Wl);
    float* OUT = (float*)d_out;

    // 0) convert weights to hi/lo bf16
    auto cvt = [&](const float* src, long off, int n) {
        cvt_split_kernel<<<(n/4 + 255)/256, 256>>>((const float4*)src, Wh + off, Wl + off, n/4);
    };
    cvt(g1_W, OFF_G1, CC*CC);
    cvt(g2_W, OFF_G2, CC*CC);
    cvt(m1_W, OFF_M1, TD*TD);
    cvt(m2_W, OFF_M2, TD*TD);
    cvt(gs_W, OFF_GS, CC*CD);
    cvt(ms_W, OFF_MS, (CD/2)*CC);
    cvt(r1_W, OFF_R1, CC*CC);
    cvt(r2_W, OFF_R2, TD*CC);

    // 1) xln = LN(x)  (fp32 + split)
    ln_split_kernel<<<ROWS, 256>>>(x, ln1_g, ln1_b, XLN, XLNh, XLNl, CC);

    // 2) style scales
    style_s_kernel<<<(BB*TD + 255)/256, 256>>>(w, s1_W, s1_b, S1, 0, TD);
    style_s_kernel<<<(BB*TD + 255)/256, 256>>>(w, s2_W, s2_b, S2, 0, TD);
    style_s_kernel<<<(BB*(CD/2) + 255)/256, 256>>>(w, ss_W, ss_b, SS, 1, CD/2);

    // 3) h1 branch
    gemm_bf3<false,false,false,true><<<dim3(CC/128, ROWS/128, 1), 256>>>(
        XLNh, XLNl, Wh+OFF_G1, Wl+OFF_G1, g1_b, nullptr, HF, nullptr, nullptr,
        CC, CC, CC, CC, 0, 0, 0, 0);
    glu_split_kernel<<<(ROWS*(TD/4) + 255)/256, 256>>>(
        (const float4*)HF, (const float4*)S1, ACTh, ACTl, TD/4, ROWS);
    gemm_bf3<false,true,true,false><<<dim3(TD/128, ROWS/128, 1), 256>>>(   // H1 transposed
        ACTh, ACTl, Wh+OFF_M1, Wl+OFF_M1, m1_b, nullptr, nullptr, H1h, H1l,
        TD, TD, TD, TD, 0, 0, 0, 0);

    // 4) h2 branch
    gemm_bf3<false,false,false,true><<<dim3(CC/128, ROWS/128, 1), 256>>>(
        XLNh, XLNl, Wh+OFF_G2, Wl+OFF_G2, g2_b, nullptr, HF, nullptr, nullptr,
        CC, CC, CC, CC, 0, 0, 0, 0);
    glu_split_kernel<<<(ROWS*(TD/4) + 255)/256, 256>>>(
        (const float4*)HF, (const float4*)S2, ACTh, ACTl, TD/4, ROWS);
    gemm_bf3<false,true,false,false><<<dim3(TD/128, ROWS/128, 1), 256>>>(
        ACTh, ACTl, Wh+OFF_M2, Wl+OFF_M2, m2_b, nullptr, nullptr, H2h, H2l,
        TD, TD, TD, TD, 0, 0, 0, 0);

    // 5) mix[b] = gelu(H1T[b] @ xln[b])   M=TD, N=CC, K=TT
    gemm_bf3<true,true,false,false><<<dim3(CC/128, TD/128, BB), 256>>>(
        H1h, H1l, XLNh, XLNl, nullptr, nullptr, nullptr, MIXh, MIXl,
        CC, TT, TT, CC, (long)TD*TT, (long)TT*CC, (long)TD*CC, 0);

    // 6) x2[b] = h2[b] @ mix[b] + xln[b]  M=TT, N=CC, K=TD
    gemm_bf3<false,false,false,true><<<dim3(CC/128, TT/128, BB), 256>>>(
        H2h, H2l, MIXh, MIXl, nullptr, XLN, X2, nullptr, nullptr,
        CC, TD, TD, CC, (long)TT*TD, (long)TD*CC, (long)TT*CC, (long)TT*CC);

    // 7) second style block
    ln_split_kernel<<<ROWS, 256>>>(X2, ln2_g, ln2_b, nullptr, XLNh, XLNl, CC);
    gemm_bf3<false,false,false,true><<<dim3(CD/128, ROWS/128, 1), 256>>>(
        XLNh, XLNl, Wh+OFF_GS, Wl+OFF_GS, gs_b, nullptr, HF, nullptr, nullptr,
        CD, CC, CC, CD, 0, 0, 0, 0);
    glu_split_kernel<<<(ROWS*(CD/8) + 255)/256, 256>>>(
        (const float4*)HF, (const float4*)SS, ACTh, ACTl, CD/8, ROWS);
    gemm_bf3<false,true,false,false><<<dim3(CC/128, ROWS/128, 1), 256>>>(   // X3 = . + ms_b + X2
        ACTh, ACTl, Wh+OFF_MS, Wl+OFF_MS, ms_b, X2, nullptr, X3h, X3l,
        CC, CD/2, CD/2, CC, 0, 0, 0, 0);

    // 8) output head
    gemm_bf3<false,false,false,true><<<dim3(CC/128, ROWS/128, 1), 256>>>(
        X3h, X3l, Wh+OFF_R1, Wl+OFF_R1, r1_b, nullptr, HF, nullptr, nullptr,
        CC, CC, CC, CC, 0, 0, 0, 0);
    glu_split_kernel<<<(ROWS*(TD/4) + 255)/256, 256>>>(
        (const float4*)HF, nullptr, ACTh, ACTl, TD/4, ROWS);
    gemm_bf3<false,false,false,true><<<dim3(CC/128, ROWS/128, 1), 256>>>(
        ACTh, ACTl, Wh+OFF_R2, Wl+OFF_R2, r2_b, nullptr, OUT, nullptr, nullptr,
        CC, TD, TD, CC, 0, 0, 0, 0);
}

// round 7
// speedup vs baseline: 1.1469x; 1.1469x over previous
#include <cuda_runtime.h>
#include <cuda_bf16.h>
#include <cstdint>

// Shapes (fixed per problem)
#define BB 8
#define TT 2048
#define CC 768
#define WDIM 512
#define TD 384
#define CD 3072
#define ROWS (BB * TT)          // 16384

// weight pack offsets (elements), layout (K, N) n-contiguous
#define OFF_G1 0
#define OFF_G2 589824
#define OFF_M1 1179648
#define OFF_M2 1327104
#define OFF_GS 1474560
#define OFF_MS 3833856
#define OFF_R1 5013504
#define OFF_R2 5603328
#define WTOT   5898240

typedef __nv_bfloat16 bf16;

// ---------------- scratch (device globals; no allocation allowed) ----------
__device__ float BUF_XLN[ROWS * CC];       // fp32 ln1 out (residual for step6)
__device__ float BUF_X2 [ROWS * CC];       // fp32 (residual for ms + ln2 in)
__device__ float BUF_S1 [BB * TD];
__device__ float BUF_S2 [BB * TD];
__device__ float BUF_SS [BB * (CD/2)];
__device__ float BUF_BI [CC + CC + CD + CC];   // interleaved biases g1,g2,gs,r1

__device__ bf16 S_XLNh[ROWS * CC],      S_XLNl[ROWS * CC];
__device__ bf16 S_ACTh[ROWS * (CD/2)],  S_ACTl[ROWS * (CD/2)];
__device__ bf16 S_H1h [BB * TD * TT],   S_H1l [BB * TD * TT];   // (b,d,t)
__device__ bf16 S_H2h [ROWS * TD],      S_H2l [ROWS * TD];      // (b,t,d)
__device__ bf16 S_MIXh[BB * TD * CC],   S_MIXl[BB * TD * CC];   // (b,d,c)
__device__ bf16 S_X3h [ROWS * CC],      S_X3l [ROWS * CC];
__device__ bf16 S_Wh  [WTOT],           S_Wl  [WTOT];

// ---------------- helpers ---------------------------------------------------
__device__ __forceinline__ float gelu_f(float v) {
    return 0.5f * v * (1.0f + erff(v * 0.70710678118654752f));
}
__device__ __forceinline__ void split_bf16(float v, bf16& h, bf16& l) {
    h = __float2bfloat16_rn(v);
    l = __float2bfloat16_rn(v - __bfloat162float(h));
}
__device__ __forceinline__ void cp16(void* smem, const void* gmem) {
    uint32_t s = (uint32_t)__cvta_generic_to_shared(smem);
    asm volatile("cp.async.cg.shared.global [%0], [%1], 16;" :: "r"(s), "l"(gmem));
}
__device__ __forceinline__ void cp_commit() { asm volatile("cp.async.commit_group;"); }

__device__ __forceinline__ void ldsm4(uint32_t* r, const void* p) {
    uint32_t a = (uint32_t)__cvta_generic_to_shared(p);
    asm volatile("ldmatrix.sync.aligned.m8n8.x4.shared.b16 {%0,%1,%2,%3}, [%4];"
                 : "=r"(r[0]), "=r"(r[1]), "=r"(r[2]), "=r"(r[3]) : "r"(a));
}
__device__ __forceinline__ void ldsm4t(uint32_t* r, const void* p) {
    uint32_t a = (uint32_t)__cvta_generic_to_shared(p);
    asm volatile("ldmatrix.sync.aligned.m8n8.x4.trans.shared.b16 {%0,%1,%2,%3}, [%4];"
                 : "=r"(r[0]), "=r"(r[1]), "=r"(r[2]), "=r"(r[3]) : "r"(a));
}
__device__ __forceinline__ void mma_bf16(float* d, const uint32_t* a, const uint32_t* b) {
    asm volatile(
        "mma.sync.aligned.m16n8k16.row.col.f32.bf16.bf16.f32 "
        "{%0,%1,%2,%3}, {%4,%5,%6,%7}, {%8,%9}, {%0,%1,%2,%3};"
        : "+f"(d[0]), "+f"(d[1]), "+f"(d[2]), "+f"(d[3])
        : "r"(a[0]), "r"(a[1]), "r"(a[2]), "r"(a[3]), "r"(b[0]), "r"(b[1]));
}

// ---------------- LayerNorm (+ bf16 split output) ----------------------------
__global__ void ln_split_kernel(const float* __restrict__ x,
                                const float* __restrict__ g,
                                const float* __restrict__ b,
                                float* __restrict__ yf,
                                bf16* __restrict__ yh,
                                bf16* __restrict__ yl, int C) {
    __shared__ float red[2][8];
    long row = blockIdx.x;
    const float* xr = x + row * C;
    float s = 0.f, s2 = 0.f;
    for (int c = threadIdx.x; c < C; c += blockDim.x) {
        float v = xr[c];
        s += v; s2 += v * v;
    }
    #pragma unroll
    for (int o = 16; o; o >>= 1) {
        s  += __shfl_xor_sync(0xFFFFFFFFu, s,  o);
        s2 += __shfl_xor_sync(0xFFFFFFFFu, s2, o);
    }
    int w = threadIdx.x >> 5, l = threadIdx.x & 31;
    if (l == 0) { red[0][w] = s; red[1][w] = s2; }
    __syncthreads();
    if (threadIdx.x < 32) {
        s  = (l < 8) ? red[0][l] : 0.f;
        s2 = (l < 8) ? red[1][l] : 0.f;
        #pragma unroll
        for (int o = 4; o; o >>= 1) {
            s  += __shfl_xor_sync(0xFFFFFFFFu, s,  o);
            s2 += __shfl_xor_sync(0xFFFFFFFFu, s2, o);
        }
        if (l == 0) { red[0][0] = s; red[1][0] = s2; }
    }
    __syncthreads();
    float mu  = red[0][0] / C;
    float var = red[1][0] / C - mu * mu;
    float inv = rsqrtf(var + 1e-6f);
    for (int c = threadIdx.x; c < C; c += blockDim.x) {
        float v = (xr[c] - mu) * inv * g[c] + b[c];
        if (yf) yf[row * C + c] = v;
        bf16 h, lo;
        split_bf16(v, h, lo);
        yh[row * C + c] = h;
        yl[row * C + c] = lo;
    }
}

// ---------------- plain weight -> hi/lo bf16 split ---------------------------
__global__ void cvt_split_kernel(const float4* __restrict__ in,
                                 bf16* __restrict__ oh,
                                 bf16* __restrict__ ol, int n4) {
    int idx = blockIdx.x * blockDim.x + threadIdx.x;
    if (idx >= n4) return;
    float4 v = in[idx];
    bf16 h[4], l[4];
    split_bf16(v.x, h[0], l[0]); split_bf16(v.y, h[1], l[1]);
    split_bf16(v.z, h[2], l[2]); split_bf16(v.w, h[3], l[3]);
    *(__nv_bfloat162*)(oh + 4L*idx    ) = __nv_bfloat162(h[0], h[1]);
    *(__nv_bfloat162*)(oh + 4L*idx + 2) = __nv_bfloat162(h[2], h[3]);
    *(__nv_bfloat162*)(ol + 4L*idx    ) = __nv_bfloat162(l[0], l[1]);
    *(__nv_bfloat162*)(ol + 4L*idx + 2) = __nv_bfloat162(l[2], l[3]);
}

// ---------------- GLU weight pack: interleave (a_j, gate_j) columns ----------
// In:  W (K, H) n-contig, bias b[H].  Out col n: src = even ? n/2 : n/2 + H/2
__global__ void glu_pack_w(const float* __restrict__ W,
                           const float* __restrict__ b,
                           bf16* __restrict__ oh, bf16* __restrict__ ol,
                           float* __restrict__ biasI, long total, int H) {
    long idx = (long)blockIdx.x * blockDim.x + threadIdx.x;
    if (idx >= total) return;
    long k = idx / H;
    int  n = (int)(idx - k * H);
    int  src = (n & 1) ? (n >> 1) + (H >> 1) : (n >> 1);
    bf16 h, l;
    split_bf16(W[k * H + src], h, l);
    oh[idx] = h;
    ol[idx] = l;
    if (k == 0) biasI[n] = b[src];
}

// ---------------- tiny style-projection -------------------------------------
__global__ void style_s_kernel(const float* __restrict__ w,
                               const float* __restrict__ sW,
                               const float* __restrict__ sb,
                               float* __restrict__ out, int sel, int N) {
    int idx = blockIdx.x * blockDim.x + threadIdx.x;
    if (idx >= BB * N) return;
    int bi = idx / N, n = idx - bi * N;
    const float* wr = w + bi * (2 * WDIM) + sel * WDIM;
    float acc = sb[n];
    for (int k = 0; k < WDIM; k++) acc += wr[k] * sW[(long)k * N + n];
    out[idx] = acc;
}

// ---------------- bf16x3 mma.sync GEMM, BK=32 double-buffered ----------------
// C(M,N) = (Ah+Al)(M,K) @ (Bh+Bl)(K,N)  (lo*lo dropped)
// A k-contig (lda), B n-contig (ldb). CTA 128x128x32, 256 thr, 8 warps 2x4.
// As: [m][k] stride 40 bf16; Bs: [k][n] stride 136 bf16. Dynamic smem.
#define ASTR 40
#define BSTR 136
#define SM_A (128 * ASTR)          // bf16 elems per A array
#define SM_B (32 * BSTR)
#define SMEMB ((4 * SM_A + 4 * SM_B) * 2)   // bytes

template <bool GLU, bool GELU, bool SPLIT, bool TRANSO, bool FP32O>
__global__ __launch_bounds__(256) void gemm_v2(
    const bf16* __restrict__ Ah, const bf16* __restrict__ Al,
    const bf16* __restrict__ Bh, const bf16* __restrict__ Bl,
    const float* __restrict__ bias, const float* __restrict__ styleS,
    const float* __restrict__ res,
    float* __restrict__ Cf, bf16* __restrict__ Ch, bf16* __restrict__ Cl,
    int N, int K, int lda, int ldb,
    long sA, long sB, long sC, long sRes)
{
    extern __shared__ char smem[];
    bf16* sAp = (bf16*)smem;                       // [st][hl][SM_A]
    bf16* sBp = (bf16*)(smem + 4 * SM_A * 2);      // [st][hl][SM_B]

    const int z = blockIdx.z;
    const bf16* Agh = Ah + (long)z * sA;
    const bf16* Agl = Al + (long)z * sA;
    const bf16* Bgh = Bh + (long)z * sB;
    const bf16* Bgl = Bl + (long)z * sB;
    const float* resp = res ? res + (long)z * sRes : nullptr;

    const int m0 = blockIdx.y * 128, n0 = blockIdx.x * 128;
    const int tid = threadIdx.x;
    const int lane = tid & 31, wid = tid >> 5;
    const int wm = wid >> 2, wn = wid & 3;
    const int lr = lane >> 2, lc = lane & 3;

    const int aoffL = (lane & 15) * ASTR + ((lane >> 4) << 3);   // + ks*16
    const int boffC = ((lane >> 4) << 3);                        // col part

    float acc[4][4][4];
    #pragma unroll
    for (int i = 0; i < 4; i++)
        #pragma unroll
        for (int j = 0; j < 4; j++) {
            acc[i][j][0] = 0.f; acc[i][j][1] = 0.f;
            acc[i][j][2] = 0.f; acc[i][j][3] = 0.f;
        }

    auto loadStage = [&](int st, int k0) {
        bf16* ah = sAp + (st * 2 + 0) * SM_A;
        bf16* al = sAp + (st * 2 + 1) * SM_A;
        #pragma unroll
        for (int i = tid; i < 512; i += 256) {
            const int r = i >> 2, c = i & 3;
            const long go = (long)(m0 + r) * lda + k0 + c * 8;
            const int so = r * ASTR + c * 8;
            cp16(ah + so, Agh + go);
            cp16(al + so, Agl + go);
        }
        bf16* bh = sBp + (st * 2 + 0) * SM_B;
        bf16* bl = sBp + (st * 2 + 1) * SM_B;
        #pragma unroll
        for (int i = tid; i < 512; i += 256) {
            const int r = i >> 4, c = i & 15;
            const long go = (long)(k0 + r) * ldb + n0 + c * 8;
            const int so = r * BSTR + c * 8;
            cp16(bh + so, Bgh + go);
            cp16(bl + so, Bgl + go);
        }
        cp_commit();
    };

    const int NST = K >> 5;
    loadStage(0, 0);
    if (NST > 1) loadStage(1, 32);

    for (int it = 0; it < NST; it++) {
        const int st = it & 1;
        if (it + 1 < NST) asm volatile("cp.async.wait_group 1;" ::: "memory");
        else              asm volatile("cp.async.wait_group 0;" ::: "memory");
        __syncthreads();

        const bf16* ah = sAp + (st * 2 + 0) * SM_A;
        const bf16* al = sAp + (st * 2 + 1) * SM_A;
        const bf16* bh = sBp + (st * 2 + 0) * SM_B;
        const bf16* bl = sBp + (st * 2 + 1) * SM_B;

        #pragma unroll
        for (int ks = 0; ks < 2; ks++) {
            uint32_t fAh[4][4], fAl[4][4], fBh[4][2], fBl[4][2];
            const int aoff = aoffL + ks * 16;
            #pragma unroll
            for (int mt = 0; mt < 4; mt++) {
                const int mb = (wm * 64 + mt * 16) * ASTR + aoff;
                ldsm4(fAh[mt], ah + mb);
                ldsm4(fAl[mt], al + mb);
            }
            const int brow = (ks * 16 + (lane & 15)) * BSTR + boffC;
            #pragma unroll
            for (int p = 0; p < 2; p++) {
                const int nb = brow + wn * 32 + p * 16;
                uint32_t r[4];
                ldsm4t(r, bh + nb);
                fBh[2*p][0] = r[0]; fBh[2*p][1] = r[1];
                fBh[2*p+1][0] = r[2]; fBh[2*p+1][1] = r[3];
                ldsm4t(r, bl + nb);
                fBl[2*p][0] = r[0]; fBl[2*p][1] = r[1];
                fBl[2*p+1][0] = r[2]; fBl[2*p+1][1] = r[3];
            }
            #pragma unroll
            for (int mt = 0; mt < 4; mt++)
                #pragma unroll
                for (int nt = 0; nt < 4; nt++) {
                    mma_bf16(acc[mt][nt], fAh[mt], fBh[nt]);
                    mma_bf16(acc[mt][nt], fAh[mt], fBl[nt]);
                    mma_bf16(acc[mt][nt], fAl[mt], fBh[nt]);
                }
        }
        __syncthreads();
        if (it + 2 < NST) loadStage(st, (it + 2) << 5);
    }

    // ---- epilogue ----
    #pragma unroll
    for (int mt = 0; mt < 4; mt++) {
        #pragma unroll
        for (int half = 0; half < 2; half++) {
            const int row = m0 + wm * 64 + mt * 16 + lr + half * 8;
            #pragma unroll
            for (int nt = 0; nt < 4; nt++) {
                const int col = n0 + wn * 32 + nt * 8 + 2 * lc;
                float v0 = acc[mt][nt][2 * half + 0];
                float v1 = acc[mt][nt][2 * half + 1];
                if (GLU) {
                    v0 += bias[col];
                    v1 += bias[col + 1];
                    float gv = v0 / (1.f + __expf(-v1));
                    const int j = col >> 1;
                    if (styleS) gv *= styleS[(row >> 11) * (N >> 1) + j];
                    bf16 h, l;
                    split_bf16(gv, h, l);
                    const long o = (long)row * (N >> 1) + j;
                    Ch[o] = h;
                    Cl[o] = l;
                } else {
                    if (bias) { v0 += bias[col]; v1 += bias[col + 1]; }
                    const long off = (long)row * N + col;
                    if (resp) {
                        float2 rv = *(const float2*)&resp[off];
                        v0 += rv.x; v1 += rv.y;
                    }
                    if (GELU) { v0 = gelu_f(v0); v1 = gelu_f(v1); }
                    if (FP32O) {
                        *(float2*)&Cf[(long)z * sC + off] = make_float2(v0, v1);
                    }
                    if (SPLIT) {
                        bf16 h0, l0, h1, l1;
                        split_bf16(v0, h0, l0);
                        split_bf16(v1, h1, l1);
                        if (TRANSO) {
                            // H1: (b,d,t)  b = row>>11, t = row&2047, d = col
                            const long o0 = ((long)(row >> 11) * TD + col) * TT + (row & 2047);
                            const long o1 = o0 + TT;
                            Ch[o0] = h0; Ch[o1] = h1;
                            Cl[o0] = l0; Cl[o1] = l1;
                        } else {
                            const long o = (long)z * sC + off;
                            *(__nv_bfloat162*)(Ch + o) = __nv_bfloat162(h0, h1);
                            *(__nv_bfloat162*)(Cl + o) = __nv_bfloat162(l0, l1);
                        }
                    }
                }
            }
        }
    }
}

// ---------------- host side --------------------------------------------------
static void* symp(const void* s) {
    void* p = nullptr;
    cudaGetSymbolAddress(&p, s);
    return p;
}

extern "C" void kernel_launch(void* const* d_in, const int* in_sizes, int n_in,
                              void* d_out, int out_size) {
    const float* x     = (const float*)d_in[0];
    const float* w     = (const float*)d_in[1];
    const float* ln1_g = (const float*)d_in[2];
    const float* ln1_b = (const float*)d_in[3];
    const float* ln2_g = (const float*)d_in[4];
    const float* ln2_b = (const float*)d_in[5];
    const float* g1_W  = (const float*)d_in[6];
    const float* g1_b  = (const float*)d_in[7];
    const float* s1_W  = (const float*)d_in[8];
    const float* s1_b  = (const float*)d_in[9];
    const float* m1_W  = (const float*)d_in[10];
    const float* m1_b  = (const float*)d_in[11];
    const float* g2_W  = (const float*)d_in[12];
    const float* g2_b  = (const float*)d_in[13];
    const float* s2_W  = (const float*)d_in[14];
    const float* s2_b  = (const float*)d_in[15];
    const float* m2_W  = (const float*)d_in[16];
    const float* m2_b  = (const float*)d_in[17];
    const float* gs_W  = (const float*)d_in[18];
    const float* gs_b  = (const float*)d_in[19];
    const float* ss_W  = (const float*)d_in[20];
    const float* ss_b  = (const float*)d_in[21];
    const float* ms_W  = (const float*)d_in[22];
    const float* ms_b  = (const float*)d_in[23];
    const float* r1_W  = (const float*)d_in[24];
    const float* r1_b  = (const float*)d_in[25];
    const float* r2_W  = (const float*)d_in[26];
    const float* r2_b  = (const float*)d_in[27];

    float* XLN = (float*)symp(BUF_XLN);
    float* X2  = (float*)symp(BUF_X2);
    float* S1  = (float*)symp(BUF_S1);
    float* S2  = (float*)symp(BUF_S2);
    float* SS  = (float*)symp(BUF_SS);
    float* BI  = (float*)symp(BUF_BI);
    bf16* XLNh = (bf16*)symp(S_XLNh);  bf16* XLNl = (bf16*)symp(S_XLNl);
    bf16* ACTh = (bf16*)symp(S_ACTh);  bf16* ACTl = (bf16*)symp(S_ACTl);
    bf16* H1h  = (bf16*)symp(S_H1h);   bf16* H1l  = (bf16*)symp(S_H1l);
    bf16* H2h  = (bf16*)symp(S_H2h);   bf16* H2l  = (bf16*)symp(S_H2l);
    bf16* MIXh = (bf16*)symp(S_MIXh);  bf16* MIXl = (bf16*)symp(S_MIXl);
    bf16* X3h  = (bf16*)symp(S_X3h);   bf16* X3l  = (bf16*)symp(S_X3l);
    bf16* Wh   = (bf16*)symp(S_Wh);    bf16* Wl   = (bf16*)symp(S_Wl);
    float* OUT = (float*)d_out;

    // dynamic smem opt-in (idempotent)
    cudaFuncSetAttribute(gemm_v2<true,  false, false, false, false>,
                         cudaFuncAttributeMaxDynamicSharedMemorySize, SMEMB);
    cudaFuncSetAttribute(gemm_v2<false, false, true,  true,  false>,
                         cudaFuncAttributeMaxDynamicSharedMemorySize, SMEMB);
    cudaFuncSetAttribute(gemm_v2<false, false, true,  false, false>,
                         cudaFuncAttributeMaxDynamicSharedMemorySize, SMEMB);
    cudaFuncSetAttribute(gemm_v2<false, true,  true,  false, false>,
                         cudaFuncAttributeMaxDynamicSharedMemorySize, SMEMB);
    cudaFuncSetAttribute(gemm_v2<false, false, false, false, true>,
                         cudaFuncAttributeMaxDynamicSharedMemorySize, SMEMB);

    // 0) weight prep
    glu_pack_w<<<(long)(CC*CC  + 255)/256, 256>>>(g1_W, g1_b, Wh+OFF_G1, Wl+OFF_G1, BI,        (long)CC*CC,  CC);
    glu_pack_w<<<(long)(CC*CC  + 255)/256, 256>>>(g2_W, g2_b, Wh+OFF_G2, Wl+OFF_G2, BI+CC,     (long)CC*CC,  CC);
    glu_pack_w<<<(long)(CC*CD  + 255)/256, 256>>>(gs_W, gs_b, Wh+OFF_GS, Wl+OFF_GS, BI+2*CC,   (long)CC*CD,  CD);
    glu_pack_w<<<(long)(CC*CC  + 255)/256, 256>>>(r1_W, r1_b, Wh+OFF_R1, Wl+OFF_R1, BI+2*CC+CD,(long)CC*CC,  CC);
    cvt_split_kernel<<<(TD*TD/4       + 255)/256, 256>>>((const float4*)m1_W, Wh+OFF_M1, Wl+OFF_M1, TD*TD/4);
    cvt_split_kernel<<<(TD*TD/4       + 255)/256, 256>>>((const float4*)m2_W, Wh+OFF_M2, Wl+OFF_M2, TD*TD/4);
    cvt_split_kernel<<<((CD/2)*CC/4   + 255)/256, 256>>>((const float4*)ms_W, Wh+OFF_MS, Wl+OFF_MS, (CD/2)*CC/4);
    cvt_split_kernel<<<(TD*CC/4       + 255)/256, 256>>>((const float4*)r2_W, Wh+OFF_R2, Wl+OFF_R2, TD*CC/4);

    // 1) xln = LN(x)
    ln_split_kernel<<<ROWS, 256>>>(x, ln1_g, ln1_b, XLN, XLNh, XLNl, CC);

    // 2) style scales
    style_s_kernel<<<(BB*TD + 255)/256, 256>>>(w, s1_W, s1_b, S1, 0, TD);
    style_s_kernel<<<(BB*TD + 255)/256, 256>>>(w, s2_W, s2_b, S2, 0, TD);
    style_s_kernel<<<(BB*(CD/2) + 255)/256, 256>>>(w, ss_W, ss_b, SS, 1, CD/2);

    // 3) h1 branch: ACT = glu(xln@G1int)*S1 ; H1(trans) = ACT@M1 + b
    gemm_v2<true, false, false, false, false><<<dim3(CC/128, ROWS/128, 1), 256, SMEMB>>>(
        XLNh, XLNl, Wh+OFF_G1, Wl+OFF_G1, BI, S1, nullptr,
        nullptr, ACTh, ACTl, CC, CC, CC, CC, 0, 0, 0, 0);
    gemm_v2<false, false, true, true, false><<<dim3(TD/128, ROWS/128, 1), 256, SMEMB>>>(
        ACTh, ACTl, Wh+OFF_M1, Wl+OFF_M1, m1_b, nullptr, nullptr,
        nullptr, H1h, H1l, TD, TD, TD, TD, 0, 0, 0, 0);

    // 4) h2 branch
    gemm_v2<true, false, false, false, false><<<dim3(CC/128, ROWS/128, 1), 256, SMEMB>>>(
        XLNh, XLNl, Wh+OFF_G2, Wl+OFF_G2, BI+CC, S2, nullptr,
        nullptr, ACTh, ACTl, CC, CC, CC, CC, 0, 0, 0, 0);
    gemm_v2<false, false, true, false, false><<<dim3(TD/128, ROWS/128, 1), 256, SMEMB>>>(
        ACTh, ACTl, Wh+OFF_M2, Wl+OFF_M2, m2_b, nullptr, nullptr,
        nullptr, H2h, H2l, TD, TD, TD, TD, 0, 0, 0, 0);

    // 5) mix[b,d,c] = gelu(sum_t H1[b,d,t] * XLN[b,t,c])   M=TD, N=CC, K=TT
    gemm_v2<false, true, true, false, false><<<dim3(CC/128, TD/128, BB), 256, SMEMB>>>(
        H1h, H1l, XLNh, XLNl, nullptr, nullptr, nullptr,
        nullptr, MIXh, MIXl, CC, TT, TT, CC,
        (long)TD*TT, (long)TT*CC, (long)TD*CC, 0);

    // 6) x2[b,t,c] = sum_d H2[b,t,d] * MIX[b,d,c] + xln    M=TT, N=CC, K=TD
    gemm_v2<false, false, false, false, true><<<dim3(CC/128, TT/128, BB), 256, SMEMB>>>(
        H2h, H2l, MIXh, MIXl, nullptr, nullptr, XLN,
        X2, nullptr, nullptr, CC, TD, TD, CC,
        (long)TT*TD, (long)TD*CC, (long)TT*CC, (long)TT*CC);

    // 7) second style block
    ln_split_kernel<<<ROWS, 256>>>(X2, ln2_g, ln2_b, nullptr, XLNh, XLNl, CC);
    gemm_v2<true, false, false, false, false><<<dim3(CD/128, ROWS/128, 1), 256, SMEMB>>>(
        XLNh, XLNl, Wh+OFF_GS, Wl+OFF_GS, BI+2*CC, SS, nullptr,
        nullptr, ACTh, ACTl, CD, CC, CC, CD, 0, 0, 0, 0);
    gemm_v2<false, false, true, false, false><<<dim3(CC/128, ROWS/128, 1), 256, SMEMB>>>(
        ACTh, ACTl, Wh+OFF_MS, Wl+OFF_MS, ms_b, nullptr, X2,
        nullptr, X3h, X3l, CC, CD/2, CD/2, CC, 0, 0, 0, 0);

    // 8) output head
    gemm_v2<true, false, false, false, false><<<dim3(CC/128, ROWS/128, 1), 256, SMEMB>>>(
        X3h, X3l, Wh+OFF_R1, Wl+OFF_R1, BI+2*CC+CD, nullptr, nullptr,
        nullptr, ACTh, ACTl, CC, CC, CC, CC, 0, 0, 0, 0);
    gemm_v2<false, false, false, false, true><<<dim3(CC/128, ROWS/128, 1), 256, SMEMB>>>(
        ACTh, ACTl, Wh+OFF_R2, Wl+OFF_R2, r2_b, nullptr, nullptr,
        OUT, nullptr, nullptr, CC, TD, TD, CC, 0, 0, 0, 0);
}

// round 8
// speedup vs baseline: 1.2133x; 1.0579x over previous
#include <cuda_runtime.h>
#include <cuda_bf16.h>
#include <cstdint>

// Shapes (fixed per problem)
#define BB 8
#define TT 2048
#define CC 768
#define WDIM 512
#define TD 384
#define CD 3072
#define ROWS (BB * TT)          // 16384

// weight pack offsets (elements), layout (K, N) n-contiguous
#define OFF_G1 0
#define OFF_G2 589824
#define OFF_M1 1179648
#define OFF_M2 1327104
#define OFF_GS 1474560
#define OFF_MS 3833856
#define OFF_R1 5013504
#define OFF_R2 5603328
#define WTOT   5898240

typedef __nv_bfloat16 bf16;

// ---------------- scratch (device globals; no allocation allowed) ----------
__device__ float BUF_XLN[ROWS * CC];       // fp32 ln1 out (residual for step6)
__device__ float BUF_X2 [ROWS * CC];       // fp32 (residual for ms + ln2 in)
__device__ float BUF_S1 [BB * TD];
__device__ float BUF_S2 [BB * TD];
__device__ float BUF_SS [BB * (CD/2)];
__device__ float BUF_BI [CC + CC + CD + CC];   // interleaved biases g1,g2,gs,r1

__device__ bf16 S_XLNh[ROWS * CC],      S_XLNl[ROWS * CC];
__device__ bf16 S_ACTh[ROWS * (CD/2)],  S_ACTl[ROWS * (CD/2)];
__device__ bf16 S_H1h [BB * TD * TT],   S_H1l [BB * TD * TT];   // (b,d,t)
__device__ bf16 S_H2h [ROWS * TD],      S_H2l [ROWS * TD];      // (b,t,d)
__device__ bf16 S_MIXh[BB * TD * CC],   S_MIXl[BB * TD * CC];   // (b,d,c)
__device__ bf16 S_X3h [ROWS * CC],      S_X3l [ROWS * CC];
__device__ bf16 S_Wh  [WTOT],           S_Wl  [WTOT];

// ---------------- helpers ---------------------------------------------------
__device__ __forceinline__ float gelu_f(float v) {
    return 0.5f * v * (1.0f + erff(v * 0.70710678118654752f));
}
__device__ __forceinline__ void split_bf16(float v, bf16& h, bf16& l) {
    h = __float2bfloat16_rn(v);
    l = __float2bfloat16_rn(v - __bfloat162float(h));
}
__device__ __forceinline__ void cp16(void* smem, const void* gmem) {
    uint32_t s = (uint32_t)__cvta_generic_to_shared(smem);
    asm volatile("cp.async.cg.shared.global [%0], [%1], 16;" :: "r"(s), "l"(gmem));
}
__device__ __forceinline__ void cp_commit() { asm volatile("cp.async.commit_group;"); }

__device__ __forceinline__ void ldsm4(uint32_t* r, const void* p) {
    uint32_t a = (uint32_t)__cvta_generic_to_shared(p);
    asm volatile("ldmatrix.sync.aligned.m8n8.x4.shared.b16 {%0,%1,%2,%3}, [%4];"
                 : "=r"(r[0]), "=r"(r[1]), "=r"(r[2]), "=r"(r[3]) : "r"(a));
}
__device__ __forceinline__ void ldsm4t(uint32_t* r, const void* p) {
    uint32_t a = (uint32_t)__cvta_generic_to_shared(p);
    asm volatile("ldmatrix.sync.aligned.m8n8.x4.trans.shared.b16 {%0,%1,%2,%3}, [%4];"
                 : "=r"(r[0]), "=r"(r[1]), "=r"(r[2]), "=r"(r[3]) : "r"(a));
}
__device__ __forceinline__ void mma_bf16(float* d, const uint32_t* a, const uint32_t* b) {
    asm volatile(
        "mma.sync.aligned.m16n8k16.row.col.f32.bf16.bf16.f32 "
        "{%0,%1,%2,%3}, {%4,%5,%6,%7}, {%8,%9}, {%0,%1,%2,%3};"
        : "+f"(d[0]), "+f"(d[1]), "+f"(d[2]), "+f"(d[3])
        : "r"(a[0]), "r"(a[1]), "r"(a[2]), "r"(a[3]), "r"(b[0]), "r"(b[1]));
}

// ---------------- LayerNorm (+ bf16 split output) ----------------------------
__global__ void ln_split_kernel(const float* __restrict__ x,
                                const float* __restrict__ g,
                                const float* __restrict__ b,
                                float* __restrict__ yf,
                                bf16* __restrict__ yh,
                                bf16* __restrict__ yl, int C) {
    __shared__ float red[2][8];
    long row = blockIdx.x;
    const float* xr = x + row * C;
    float s = 0.f, s2 = 0.f;
    for (int c = threadIdx.x; c < C; c += blockDim.x) {
        float v = xr[c];
        s += v; s2 += v * v;
    }
    #pragma unroll
    for (int o = 16; o; o >>= 1) {
        s  += __shfl_xor_sync(0xFFFFFFFFu, s,  o);
        s2 += __shfl_xor_sync(0xFFFFFFFFu, s2, o);
    }
    int w = threadIdx.x >> 5, l = threadIdx.x & 31;
    if (l == 0) { red[0][w] = s; red[1][w] = s2; }
    __syncthreads();
    if (threadIdx.x < 32) {
        s  = (l < 8) ? red[0][l] : 0.f;
        s2 = (l < 8) ? red[1][l] : 0.f;
        #pragma unroll
        for (int o = 4; o; o >>= 1) {
            s  += __shfl_xor_sync(0xFFFFFFFFu, s,  o);
            s2 += __shfl_xor_sync(0xFFFFFFFFu, s2, o);
        }
        if (l == 0) { red[0][0] = s; red[1][0] = s2; }
    }
    __syncthreads();
    float mu  = red[0][0] / C;
    float var = red[1][0] / C - mu * mu;
    float inv = rsqrtf(var + 1e-6f);
    for (int c = threadIdx.x; c < C; c += blockDim.x) {
        float v = (xr[c] - mu) * inv * g[c] + b[c];
        if (yf) yf[row * C + c] = v;
        bf16 h, lo;
        split_bf16(v, h, lo);
        yh[row * C + c] = h;
        yl[row * C + c] = lo;
    }
}

// ---------------- plain weight -> hi/lo bf16 split ---------------------------
__global__ void cvt_split_kernel(const float4* __restrict__ in,
                                 bf16* __restrict__ oh,
                                 bf16* __restrict__ ol, int n4) {
    int idx = blockIdx.x * blockDim.x + threadIdx.x;
    if (idx >= n4) return;
    float4 v = in[idx];
    bf16 h[4], l[4];
    split_bf16(v.x, h[0], l[0]); split_bf16(v.y, h[1], l[1]);
    split_bf16(v.z, h[2], l[2]); split_bf16(v.w, h[3], l[3]);
    *(__nv_bfloat162*)(oh + 4L*idx    ) = __nv_bfloat162(h[0], h[1]);
    *(__nv_bfloat162*)(oh + 4L*idx + 2) = __nv_bfloat162(h[2], h[3]);
    *(__nv_bfloat162*)(ol + 4L*idx    ) = __nv_bfloat162(l[0], l[1]);
    *(__nv_bfloat162*)(ol + 4L*idx + 2) = __nv_bfloat162(l[2], l[3]);
}

// ---------------- GLU weight pack: interleave (a_j, gate_j) columns ----------
__global__ void glu_pack_w(const float* __restrict__ W,
                           const float* __restrict__ b,
                           bf16* __restrict__ oh, bf16* __restrict__ ol,
                           float* __restrict__ biasI, long total, int H) {
    long idx = (long)blockIdx.x * blockDim.x + threadIdx.x;
    if (idx >= total) return;
    long k = idx / H;
    int  n = (int)(idx - k * H);
    int  src = (n & 1) ? (n >> 1) + (H >> 1) : (n >> 1);
    bf16 h, l;
    split_bf16(W[k * H + src], h, l);
    oh[idx] = h;
    ol[idx] = l;
    if (k == 0) biasI[n] = b[src];
}

// ---------------- tiny style-projection -------------------------------------
__global__ void style_s_kernel(const float* __restrict__ w,
                               const float* __restrict__ sW,
                               const float* __restrict__ sb,
                               float* __restrict__ out, int sel, int N) {
    int idx = blockIdx.x * blockDim.x + threadIdx.x;
    if (idx >= BB * N) return;
    int bi = idx / N, n = idx - bi * N;
    const float* wr = w + bi * (2 * WDIM) + sel * WDIM;
    float acc = sb[n];
    for (int k = 0; k < WDIM; k++) acc += wr[k] * sW[(long)k * N + n];
    out[idx] = acc;
}

// ---------------- bf16x3 mma.sync GEMM --------------------------------------
// C(M,N) = (Ah+Al)(M,K) @ (Bh+Bl)(K,N)  (lo*lo dropped)
// A k-contig (lda), B n-contig (ldb). CTA 128x128x32, 128 thr, 4 warps 2x2,
// warp tile 64x64. 3-stage cp.async pipeline, one __syncthreads per iter.
// As: [m][k] stride 40 bf16; Bs: [k][n] stride 136 bf16. Dynamic smem.
#define ASTR 40
#define BSTR 136
#define A_BYTES (128 * ASTR * 2)       // 10240 per hi/lo array
#define B_BYTES (32 * BSTR * 2)        // 8704 per hi/lo array
#define STAGEB  (2 * A_BYTES + 2 * B_BYTES)   // 37888
#define SMEMB   (3 * STAGEB)                  // 113664

template <bool GLU, bool GELU, bool SPLIT, bool TRANSO, bool FP32O>
__global__ __launch_bounds__(128) void gemm_v3(
    const bf16* __restrict__ Ah, const bf16* __restrict__ Al,
    const bf16* __restrict__ Bh, const bf16* __restrict__ Bl,
    const float* __restrict__ bias, const float* __restrict__ styleS,
    const float* __restrict__ res,
    float* __restrict__ Cf, bf16* __restrict__ Ch, bf16* __restrict__ Cl,
    int N, int K, int lda, int ldb,
    long sA, long sB, long sC, long sRes)
{
    extern __shared__ char smem[];

    const int z = blockIdx.z;
    const bf16* Agh = Ah + (long)z * sA;
    const bf16* Agl = Al + (long)z * sA;
    const bf16* Bgh = Bh + (long)z * sB;
    const bf16* Bgl = Bl + (long)z * sB;
    const float* resp = res ? res + (long)z * sRes : nullptr;

    const int m0 = blockIdx.y * 128, n0 = blockIdx.x * 128;
    const int tid = threadIdx.x;
    const int lane = tid & 31, wid = tid >> 5;
    const int wm = wid >> 1, wn = wid & 1;           // 2x2 warp grid, tile 64x64
    const int lr = lane >> 2, lc = lane & 3;

    const int aoffL = (lane & 15) * ASTR + ((lane >> 4) << 3);
    const int boffC = ((lane >> 4) << 3);

    float acc[4][8][4];
    #pragma unroll
    for (int i = 0; i < 4; i++)
        #pragma unroll
        for (int j = 0; j < 8; j++) {
            acc[i][j][0] = 0.f; acc[i][j][1] = 0.f;
            acc[i][j][2] = 0.f; acc[i][j][3] = 0.f;
        }

    auto loadStage = [&](int st, int k0) {
        char* base = smem + st * STAGEB;
        bf16* ah = (bf16*)(base);
        bf16* al = (bf16*)(base + A_BYTES);
        bf16* bh = (bf16*)(base + 2 * A_BYTES);
        bf16* bl = (bf16*)(base + 2 * A_BYTES + B_BYTES);
        #pragma unroll
        for (int i = tid; i < 512; i += 128) {
            const int r = i >> 2, c = i & 3;
            const long go = (long)(m0 + r) * lda + k0 + c * 8;
            const int so = r * ASTR + c * 8;
            cp16(ah + so, Agh + go);
            cp16(al + so, Agl + go);
        }
        #pragma unroll
        for (int i = tid; i < 512; i += 128) {
            const int r = i >> 4, c = i & 15;
            const long go = (long)(k0 + r) * ldb + n0 + c * 8;
            const int so = r * BSTR + c * 8;
            cp16(bh + so, Bgh + go);
            cp16(bl + so, Bgl + go);
        }
        cp_commit();
    };

    const int NST = K >> 5;
    loadStage(0, 0);
    if (NST > 1) loadStage(1, 32);

    for (int it = 0; it < NST; it++) {
        const int st = it % 3;
        if (it + 2 <= NST) asm volatile("cp.async.wait_group 1;" ::: "memory");
        else               asm volatile("cp.async.wait_group 0;" ::: "memory");
        __syncthreads();

        char* base = smem + st * STAGEB;
        const bf16* ah = (const bf16*)(base);
        const bf16* al = (const bf16*)(base + A_BYTES);
        const bf16* bh = (const bf16*)(base + 2 * A_BYTES);
        const bf16* bl = (const bf16*)(base + 2 * A_BYTES + B_BYTES);

        #pragma unroll
        for (int ks = 0; ks < 2; ks++) {
            uint32_t fAh[4][4], fAl[4][4];
            const int aoff = aoffL + ks * 16;
            #pragma unroll
            for (int mt = 0; mt < 4; mt++) {
                const int mb = (wm * 64 + mt * 16) * ASTR + aoff;
                ldsm4(fAh[mt], ah + mb);
                ldsm4(fAl[mt], al + mb);
            }
            const int brow = (ks * 16 + (lane & 15)) * BSTR + boffC;
            #pragma unroll
            for (int ph = 0; ph < 2; ph++) {      // two halves of 32 cols each
                uint32_t fBh[4][2], fBl[4][2];
                #pragma unroll
                for (int p = 0; p < 2; p++) {
                    const int nb = brow + wn * 64 + ph * 32 + p * 16;
                    uint32_t r[4];
                    ldsm4t(r, bh + nb);
                    fBh[2*p][0] = r[0]; fBh[2*p][1] = r[1];
                    fBh[2*p+1][0] = r[2]; fBh[2*p+1][1] = r[3];
                    ldsm4t(r, bl + nb);
                    fBl[2*p][0] = r[0]; fBl[2*p][1] = r[1];
                    fBl[2*p+1][0] = r[2]; fBl[2*p+1][1] = r[3];
                }
                #pragma unroll
                for (int mt = 0; mt < 4; mt++)
                    #pragma unroll
                    for (int nt = 0; nt < 4; nt++) {
                        float* a4 = acc[mt][ph * 4 + nt];
                        mma_bf16(a4, fAh[mt], fBh[nt]);
                        mma_bf16(a4, fAh[mt], fBl[nt]);
                        mma_bf16(a4, fAl[mt], fBh[nt]);
                    }
            }
        }
        if (it + 2 < NST) loadStage((it + 2) % 3, (it + 2) << 5);
    }

    // ---- epilogue ----
    #pragma unroll
    for (int mt = 0; mt < 4; mt++) {
        #pragma unroll
        for (int half = 0; half < 2; half++) {
            const int row = m0 + wm * 64 + mt * 16 + lr + half * 8;
            #pragma unroll
            for (int nt = 0; nt < 8; nt++) {
                const int col = n0 + wn * 64 + nt * 8 + 2 * lc;
                float v0 = acc[mt][nt][2 * half + 0];
                float v1 = acc[mt][nt][2 * half + 1];
                if (GLU) {
                    v0 += bias[col];
                    v1 += bias[col + 1];
                    float gv = v0 / (1.f + __expf(-v1));
                    const int j = col >> 1;
                    if (styleS) gv *= styleS[(row >> 11) * (N >> 1) + j];
                    bf16 h, l;
                    split_bf16(gv, h, l);
                    const long o = (long)row * (N >> 1) + j;
                    Ch[o] = h;
                    Cl[o] = l;
                } else {
                    if (bias) { v0 += bias[col]; v1 += bias[col + 1]; }
                    const long off = (long)row * N + col;
                    if (resp) {
                        float2 rv = *(const float2*)&resp[off];
                        v0 += rv.x; v1 += rv.y;
                    }
                    if (GELU) { v0 = gelu_f(v0); v1 = gelu_f(v1); }
                    if (FP32O) {
                        *(float2*)&Cf[(long)z * sC + off] = make_float2(v0, v1);
                    }
                    if (SPLIT) {
                        bf16 h0, l0, h1, l1;
                        split_bf16(v0, h0, l0);
                        split_bf16(v1, h1, l1);
                        if (TRANSO) {
                            // H1: (b,d,t)  b = row>>11, t = row&2047, d = col
                            const long o0 = ((long)(row >> 11) * TD + col) * TT + (row & 2047);
                            const long o1 = o0 + TT;
                            Ch[o0] = h0; Ch[o1] = h1;
                            Cl[o0] = l0; Cl[o1] = l1;
                        } else {
                            const long o = (long)z * sC + off;
                            *(__nv_bfloat162*)(Ch + o) = __nv_bfloat162(h0, h1);
                            *(__nv_bfloat162*)(Cl + o) = __nv_bfloat162(l0, l1);
                        }
                    }
                }
            }
        }
    }
}

// ---------------- host side --------------------------------------------------
static void* symp(const void* s) {
    void* p = nullptr;
    cudaGetSymbolAddress(&p, s);
    return p;
}

extern "C" void kernel_launch(void* const* d_in, const int* in_sizes, int n_in,
                              void* d_out, int out_size) {
    const float* x     = (const float*)d_in[0];
    const float* w     = (const float*)d_in[1];
    const float* ln1_g = (const float*)d_in[2];
    const float* ln1_b = (const float*)d_in[3];
    const float* ln2_g = (const float*)d_in[4];
    const float* ln2_b = (const float*)d_in[5];
    const float* g1_W  = (const float*)d_in[6];
    const float* g1_b  = (const float*)d_in[7];
    const float* s1_W  = (const float*)d_in[8];
    const float* s1_b  = (const float*)d_in[9];
    const float* m1_W  = (const float*)d_in[10];
    const float* m1_b  = (const float*)d_in[11];
    const float* g2_W  = (const float*)d_in[12];
    const float* g2_b  = (const float*)d_in[13];
    const float* s2_W  = (const float*)d_in[14];
    const float* s2_b  = (const float*)d_in[15];
    const float* m2_W  = (const float*)d_in[16];
    const float* m2_b  = (const float*)d_in[17];
    const float* gs_W  = (const float*)d_in[18];
    const float* gs_b  = (const float*)d_in[19];
    const float* ss_W  = (const float*)d_in[20];
    const float* ss_b  = (const float*)d_in[21];
    const float* ms_W  = (const float*)d_in[22];
    const float* ms_b  = (const float*)d_in[23];
    const float* r1_W  = (const float*)d_in[24];
    const float* r1_b  = (const float*)d_in[25];
    const float* r2_W  = (const float*)d_in[26];
    const float* r2_b  = (const float*)d_in[27];

    float* XLN = (float*)symp(BUF_XLN);
    float* X2  = (float*)symp(BUF_X2);
    float* S1  = (float*)symp(BUF_S1);
    float* S2  = (float*)symp(BUF_S2);
    float* SS  = (float*)symp(BUF_SS);
    float* BI  = (float*)symp(BUF_BI);
    bf16* XLNh = (bf16*)symp(S_XLNh);  bf16* XLNl = (bf16*)symp(S_XLNl);
    bf16* ACTh = (bf16*)symp(S_ACTh);  bf16* ACTl = (bf16*)symp(S_ACTl);
    bf16* H1h  = (bf16*)symp(S_H1h);   bf16* H1l  = (bf16*)symp(S_H1l);
    bf16* H2h  = (bf16*)symp(S_H2h);   bf16* H2l  = (bf16*)symp(S_H2l);
    bf16* MIXh = (bf16*)symp(S_MIXh);  bf16* MIXl = (bf16*)symp(S_MIXl);
    bf16* X3h  = (bf16*)symp(S_X3h);   bf16* X3l  = (bf16*)symp(S_X3l);
    bf16* Wh   = (bf16*)symp(S_Wh);    bf16* Wl   = (bf16*)symp(S_Wl);
    float* OUT = (float*)d_out;

    // dynamic smem opt-in (idempotent)
    cudaFuncSetAttribute(gemm_v3<true,  false, false, false, false>,
                         cudaFuncAttributeMaxDynamicSharedMemorySize, SMEMB);
    cudaFuncSetAttribute(gemm_v3<false, false, true,  true,  false>,
                         cudaFuncAttributeMaxDynamicSharedMemorySize, SMEMB);
    cudaFuncSetAttribute(gemm_v3<false, false, true,  false, false>,
                         cudaFuncAttributeMaxDynamicSharedMemorySize, SMEMB);
    cudaFuncSetAttribute(gemm_v3<false, true,  true,  false, false>,
                         cudaFuncAttributeMaxDynamicSharedMemorySize, SMEMB);
    cudaFuncSetAttribute(gemm_v3<false, false, false, false, true>,
                         cudaFuncAttributeMaxDynamicSharedMemorySize, SMEMB);

    // Launch order arranged so launch #6 is the first big GLU GEMM (ncu -s 5 -c 1)
    // 1) pack g1
    glu_pack_w<<<(long)(CC*CC + 255)/256, 256>>>(g1_W, g1_b, Wh+OFF_G1, Wl+OFF_G1, BI,
                                                 (long)CC*CC, CC);
    // 2) ln1
    ln_split_kernel<<<ROWS, 256>>>(x, ln1_g, ln1_b, XLN, XLNh, XLNl, CC);
    // 3) style S1
    style_s_kernel<<<(BB*TD + 255)/256, 256>>>(w, s1_W, s1_b, S1, 0, TD);
    // 4) pack g2
    glu_pack_w<<<(long)(CC*CC + 255)/256, 256>>>(g2_W, g2_b, Wh+OFF_G2, Wl+OFF_G2, BI+CC,
                                                 (long)CC*CC, CC);
    // 5) style S2
    style_s_kernel<<<(BB*TD + 255)/256, 256>>>(w, s2_W, s2_b, S2, 0, TD);
    // 6) GLU1 GEMM  (profiled by ncu)
    gemm_v3<true, false, false, false, false><<<dim3(CC/128, ROWS/128, 1), 128, SMEMB>>>(
        XLNh, XLNl, Wh+OFF_G1, Wl+OFF_G1, BI, S1, nullptr,
        nullptr, ACTh, ACTl, CC, CC, CC, CC, 0, 0, 0, 0);
    // 7) cvt m1
    cvt_split_kernel<<<(TD*TD/4 + 255)/256, 256>>>((const float4*)m1_W, Wh+OFF_M1, Wl+OFF_M1, TD*TD/4);
    // 8) H1(trans) = ACT@M1 + b
    gemm_v3<false, false, true, true, false><<<dim3(TD/128, ROWS/128, 1), 128, SMEMB>>>(
        ACTh, ACTl, Wh+OFF_M1, Wl+OFF_M1, m1_b, nullptr, nullptr,
        nullptr, H1h, H1l, TD, TD, TD, TD, 0, 0, 0, 0);
    // 9) style SS
    style_s_kernel<<<(BB*(CD/2) + 255)/256, 256>>>(w, ss_W, ss_b, SS, 1, CD/2);
    // 10) cvt m2
    cvt_split_kernel<<<(TD*TD/4 + 255)/256, 256>>>((const float4*)m2_W, Wh+OFF_M2, Wl+OFF_M2, TD*TD/4);
    // 11) GLU2 GEMM
    gemm_v3<true, false, false, false, false><<<dim3(CC/128, ROWS/128, 1), 128, SMEMB>>>(
        XLNh, XLNl, Wh+OFF_G2, Wl+OFF_G2, BI+CC, S2, nullptr,
        nullptr, ACTh, ACTl, CC, CC, CC, CC, 0, 0, 0, 0);
    // 12) H2 = ACT@M2 + b
    gemm_v3<false, false, true, false, false><<<dim3(TD/128, ROWS/128, 1), 128, SMEMB>>>(
        ACTh, ACTl, Wh+OFF_M2, Wl+OFF_M2, m2_b, nullptr, nullptr,
        nullptr, H2h, H2l, TD, TD, TD, TD, 0, 0, 0, 0);
    // 13) mix[b,d,c] = gelu(sum_t H1[b,d,t] * XLN[b,t,c])   M=TD, N=CC, K=TT
    gemm_v3<false, true, true, false, false><<<dim3(CC/128, TD/128, BB), 128, SMEMB>>>(
        H1h, H1l, XLNh, XLNl, nullptr, nullptr, nullptr,
        nullptr, MIXh, MIXl, CC, TT, TT, CC,
        (long)TD*TT, (long)TT*CC, (long)TD*CC, 0);
    // 14) x2[b,t,c] = sum_d H2[b,t,d] * MIX[b,d,c] + xln    M=TT, N=CC, K=TD
    gemm_v3<false, false, false, false, true><<<dim3(CC/128, TT/128, BB), 128, SMEMB>>>(
        H2h, H2l, MIXh, MIXl, nullptr, nullptr, XLN,
        X2, nullptr, nullptr, CC, TD, TD, CC,
        (long)TT*TD, (long)TD*CC, (long)TT*CC, (long)TT*CC);
    // 15) ln2
    ln_split_kernel<<<ROWS, 256>>>(X2, ln2_g, ln2_b, nullptr, XLNh, XLNl, CC);
    // 16) pack gs
    glu_pack_w<<<(long)(CC*CD + 255)/256, 256>>>(gs_W, gs_b, Wh+OFF_GS, Wl+OFF_GS, BI+2*CC,
                                                 (long)CC*CD, CD);
    // 17) GLUs GEMM
    gemm_v3<true, false, false, false, false><<<dim3(CD/128, ROWS/128, 1), 128, SMEMB>>>(
        XLNh, XLNl, Wh+OFF_GS, Wl+OFF_GS, BI+2*CC, SS, nullptr,
        nullptr, ACTh, ACTl, CD, CC, CC, CD, 0, 0, 0, 0);
    // 18) cvt ms
    cvt_split_kernel<<<((CD/2)*CC/4 + 255)/256, 256>>>((const float4*)ms_W, Wh+OFF_MS, Wl+OFF_MS, (CD/2)*CC/4);
    // 19) X3 = ACT@MS + ms_b + X2
    gemm_v3<false, false, true, false, false><<<dim3(CC/128, ROWS/128, 1), 128, SMEMB>>>(
        ACTh, ACTl, Wh+OFF_MS, Wl+OFF_MS, ms_b, nullptr, X2,
        nullptr, X3h, X3l, CC, CD/2, CD/2, CC, 0, 0, 0, 0);
    // 20) pack r1
    glu_pack_w<<<(long)(CC*CC + 255)/256, 256>>>(r1_W, r1_b, Wh+OFF_R1, Wl+OFF_R1, BI+2*CC+CD,
                                                 (long)CC*CC, CC);
    // 21) head GLU GEMM
    gemm_v3<true, false, false, false, false><<<dim3(CC/128, ROWS/128, 1), 128, SMEMB>>>(
        X3h, X3l, Wh+OFF_R1, Wl+OFF_R1, BI+2*CC+CD, nullptr, nullptr,
        nullptr, ACTh, ACTl, CC, CC, CC, CC, 0, 0, 0, 0);
    // 22) cvt r2
    cvt_split_kernel<<<(TD*CC/4 + 255)/256, 256>>>((const float4*)r2_W, Wh+OFF_R2, Wl+OFF_R2, TD*CC/4);
    // 23) OUT = ACT@R2 + b
    gemm_v3<false, false, false, false, true><<<dim3(CC/128, ROWS/128, 1), 128, SMEMB>>>(
        ACTh, ACTl, Wh+OFF_R2, Wl+OFF_R2, r2_b, nullptr, nullptr,
        OUT, nullptr, nullptr, CC, TD, TD, CC, 0, 0, 0, 0);
}